// round 4
// baseline (speedup 1.0000x reference)
#include <cuda_runtime.h>
#include <cstdint>
#include <math.h>

#define DIM 128
#define TILE 128
#define BMAX 8192
#define NTMAX 64
#define TPB 4                  // B-tiles per CTA; A tile stays resident
#define LDW 68                 // smem row stride in 32-bit words (136 bf16): banks (4g+t)%32 distinct

__device__ float g_nsk[BMAX];
__device__ float g_nim[BMAX];
__device__ uint32_t g_skbf[BMAX * 64];                    // bf16x2-packed rows
__device__ uint32_t g_imbf[BMAX * 64];
__device__ float g_partial[(size_t)BMAX * NTMAX * 2];     // per (row, bn, wn-half)
__device__ float g_diag[BMAX];
__device__ float g_rowval[BMAX];

static __device__ __forceinline__ uint32_t s2u(const void* p) {
    uint32_t a;
    asm("{ .reg .u64 t; cvta.to.shared.u64 t, %1; cvt.u32.u64 %0, t; }" : "=r"(a) : "l"(p));
    return a;
}
static __device__ __forceinline__ void cpa16(uint32_t dst, const void* src) {
    asm volatile("cp.async.cg.shared.global [%0], [%1], 16;" :: "r"(dst), "l"(src) : "memory");
}
#define CP_COMMIT() asm volatile("cp.async.commit_group;" ::: "memory")
#define CP_WAIT0()  asm volatile("cp.async.wait_group 0;" ::: "memory")

static __device__ __forceinline__ uint32_t packbf(float lo, float hi) {
    uint32_t r;
    asm("cvt.rn.bf16x2.f32 %0, %1, %2;" : "=r"(r) : "f"(hi), "f"(lo));
    return r;
}
static __device__ __forceinline__ void mma16(float* c, const uint32_t* a, const uint32_t* b) {
    asm("mma.sync.aligned.m16n8k16.row.col.f32.bf16.bf16.f32 "
        "{%0,%1,%2,%3}, {%4,%5,%6,%7}, {%8,%9}, {%0,%1,%2,%3};"
        : "+f"(c[0]), "+f"(c[1]), "+f"(c[2]), "+f"(c[3])
        : "r"(a[0]), "r"(a[1]), "r"(a[2]), "r"(a[3]), "r"(b[0]), "r"(b[1]));
}

// ---------------------------------------------------------------------------
// Fused: f32 row norms + bf16 conversion. One warp per row.
// ---------------------------------------------------------------------------
__global__ void convert_norms(const float* __restrict__ sk,
                              const float* __restrict__ im, int B) {
    int row = (blockIdx.x * blockDim.x + threadIdx.x) >> 5;
    int lane = threadIdx.x & 31;
    if (row >= B) return;
    const float* src = blockIdx.y ? im : sk;
    float* ndst = blockIdx.y ? g_nim : g_nsk;
    uint32_t* bdst = blockIdx.y ? g_imbf : g_skbf;
    float4 v = ((const float4*)(src + (size_t)row * DIM))[lane];
    bdst[row * 64 + lane * 2]     = packbf(v.x, v.y);
    bdst[row * 64 + lane * 2 + 1] = packbf(v.z, v.w);
    float s = v.x * v.x + v.y * v.y + v.z * v.z + v.w * v.w;
#pragma unroll
    for (int o = 16; o; o >>= 1) s += __shfl_xor_sync(0xffffffffu, s, o);
    if (lane == 0) ndst[row] = s;
}

// ---------------------------------------------------------------------------
// bf16 mma.sync GEMM + fused distance/exp epilogue. occ 2.
// 8 warps: 4 m-blocks x 2 n-blocks, warp tile 32x64, k-steps of 16.
// A resident; B double-buffered via cp.async (next tile issued before mainloop).
// ---------------------------------------------------------------------------
__global__ void __launch_bounds__(256, 2)
dist_mma(int nt) {
    extern __shared__ uint32_t smw[];
    const uint32_t sbase = s2u(smw);
    uint32_t* As  = smw;
    const uint32_t BOFF0 = 128 * LDW;
    const uint32_t BOFF1 = 2 * 128 * LDW;

    const int tid = threadIdx.x;
    const int wid = tid >> 5;
    const int lane = tid & 31;
    const int g = lane >> 2;
    const int t = lane & 3;
    const int wm = wid & 3;
    const int wn = wid >> 2;

    const int ntg = nt / TPB;
    const int bm = blockIdx.x / ntg;
    const int bn0 = (blockIdx.x % ntg) * TPB;

    // prologue: A tile + B tile 0 via cp.async (2048 16B chunks each, 8/thread)
    {
        const uint32_t* Ag = g_skbf + (size_t)bm * TILE * 64;
        const uint32_t* Bg = g_imbf + (size_t)bn0 * TILE * 64;
#pragma unroll
        for (int it = 0; it < 8; it++) {
            int c = it * 256 + tid;
            int row = c >> 4, ch = c & 15;
            uint32_t doff = (uint32_t)row * 272 + (uint32_t)ch * 16;
            cpa16(sbase + doff, Ag + row * 64 + ch * 4);
            cpa16(sbase + BOFF0 * 4 + doff, Bg + row * 64 + ch * 4);
        }
        CP_COMMIT();
        CP_WAIT0();
    }
    __syncthreads();

    float nr[2][2];
#pragma unroll
    for (int mt = 0; mt < 2; mt++)
#pragma unroll
        for (int h = 0; h < 2; h++)
            nr[mt][h] = g_nsk[bm * TILE + wm * 32 + mt * 16 + h * 8 + g];

    const int a_base = (wm * 32 + g) * LDW + t;
    const int b_base = (wn * 64 + g) * LDW + t;

    for (int tt = 0; tt < TPB; tt++) {
        const int bn = bn0 + tt;
        const uint32_t* Bs = smw + ((tt & 1) ? BOFF1 : BOFF0);

        // issue next B tile into the other buffer (overlaps mainloop + epilogue)
        if (tt < TPB - 1) {
            const uint32_t* Bg = g_imbf + (size_t)(bn + 1) * TILE * 64;
            uint32_t dbuf = sbase + ((tt & 1) ? BOFF0 : BOFF1) * 4;
#pragma unroll
            for (int it = 0; it < 8; it++) {
                int c = it * 256 + tid;
                int row = c >> 4, ch = c & 15;
                cpa16(dbuf + (uint32_t)row * 272 + (uint32_t)ch * 16, Bg + row * 64 + ch * 4);
            }
            CP_COMMIT();
        }

        float acc[2][8][4];
#pragma unroll
        for (int mt = 0; mt < 2; mt++)
#pragma unroll
            for (int nb = 0; nb < 8; nb++)
#pragma unroll
                for (int r = 0; r < 4; r++) acc[mt][nb][r] = 0.f;

        // mainloop: 8 k-steps of 16
#pragma unroll
        for (int ks = 0; ks < 8; ks++) {
            const int ko = ks * 8;
            uint32_t a[2][4], b[8][2];
#pragma unroll
            for (int mt = 0; mt < 2; mt++) {
                int ba = a_base + mt * 16 * LDW + ko;
                a[mt][0] = As[ba];
                a[mt][1] = As[ba + 8 * LDW];
                a[mt][2] = As[ba + 4];
                a[mt][3] = As[ba + 8 * LDW + 4];
            }
#pragma unroll
            for (int nb = 0; nb < 8; nb++) {
                int bb = b_base + nb * 8 * LDW + ko;
                b[nb][0] = Bs[bb];
                b[nb][1] = Bs[bb + 4];
            }
#pragma unroll
            for (int mt = 0; mt < 2; mt++)
#pragma unroll
                for (int nb = 0; nb < 8; nb++) mma16(acc[mt][nb], a[mt], b[nb]);
        }

        // fused epilogue: sq -> d -> exp(-d), row partials straight to gmem
        const float2* ncp = (const float2*)(g_nim + (size_t)bn * TILE + wn * 64);
        const bool isdiag = (bm == bn);
#pragma unroll
        for (int mt = 0; mt < 2; mt++) {
#pragma unroll
            for (int h = 0; h < 2; h++) {
                const int r_local = wm * 32 + mt * 16 + h * 8 + g;
                float rs = 0.f;
#pragma unroll
                for (int nb = 0; nb < 8; nb++) {
                    float2 nc = ncp[nb * 4 + t];
                    float base = nr[mt][h];
                    float sq0 = fmaxf(fmaf(-2.f, acc[mt][nb][h * 2 + 0], base + nc.x), 0.f);
                    float sq1 = fmaxf(fmaf(-2.f, acc[mt][nb][h * 2 + 1], base + nc.y), 0.f);
                    float d0, d1, e0, e1;
                    asm("sqrt.approx.f32 %0, %1;" : "=f"(d0) : "f"(sq0));
                    asm("sqrt.approx.f32 %0, %1;" : "=f"(d1) : "f"(sq1));
                    asm("ex2.approx.f32 %0, %1;" : "=f"(e0) : "f"(d0 * -1.4426950408889634f));
                    asm("ex2.approx.f32 %0, %1;" : "=f"(e1) : "f"(d1 * -1.4426950408889634f));
                    rs += e0 + e1;
                    if (isdiag) {
                        int jc = wn * 64 + nb * 8 + 2 * t;
                        if (jc == r_local) g_diag[bm * TILE + r_local] = d0;
                        if (jc + 1 == r_local) g_diag[bm * TILE + r_local] = d1;
                    }
                }
                rs += __shfl_xor_sync(0xffffffffu, rs, 1);
                rs += __shfl_xor_sync(0xffffffffu, rs, 2);
                if (t == 0)
                    g_partial[((size_t)(bm * TILE + r_local) * nt + bn) * 2 + wn] = rs;
            }
        }

        if (tt < TPB - 1) {
            CP_WAIT0();
            __syncthreads();
        }
    }
}

// ---------------------------------------------------------------------------
// Per-row: log(sum of 2*nt partials) + diag (fixed order, deterministic)
// ---------------------------------------------------------------------------
__global__ void rows_kernel(int B, int nt) {
    int i = blockIdx.x * blockDim.x + threadIdx.x;
    if (i >= B) return;
    float s = 0.f;
    const float* p = g_partial + (size_t)i * nt * 2;
    for (int t = 0; t < 2 * nt; t++) s += p[t];
    g_rowval[i] = logf(s) + g_diag[i];
}

__global__ void final_kernel(float* __restrict__ out, int B, int out_size) {
    __shared__ float sm[1024];
    int tid = threadIdx.x;
    float s = 0.f;
    for (int i = tid; i < B; i += 1024) s += g_rowval[i];
    sm[tid] = s;
    __syncthreads();
    for (int o = 512; o; o >>= 1) {
        if (tid < o) sm[tid] += sm[tid + o];
        __syncthreads();
    }
    if (tid == 0) {
        float loss = sm[0] / (float)B;
        for (int i = 0; i < out_size; i++) out[i] = loss;
    }
}

extern "C" void kernel_launch(void* const* d_in, const int* in_sizes, int n_in,
                              void* d_out, int out_size) {
    const float* sk = (const float*)d_in[0];
    const float* im = (const float*)d_in[1];
    float* out = (float*)d_out;

    int B = in_sizes[0] / DIM;   // 8192
    int nt = B / TILE;           // 64

    convert_norms<<<dim3(B / 8, 2), 256>>>(sk, im, B);

    static const int SMEM_BYTES = 3 * 128 * LDW * 4;   // 104448
    cudaFuncSetAttribute(dist_mma, cudaFuncAttributeMaxDynamicSharedMemorySize, SMEM_BYTES);
    int ncta = nt * (nt / TPB);  // 1024
    dist_mma<<<ncta, 256, SMEM_BYTES>>>(nt);

    rows_kernel<<<(B + 255) / 256, 256>>>(B, nt);
    final_kernel<<<1, 1024>>>(out, B, out_size);
}

// round 5
// speedup vs baseline: 1.4043x; 1.4043x over previous
#include <cuda_runtime.h>
#include <cstdint>
#include <math.h>

#define DIM 128
#define TILE 128
#define BMAX 8192
#define NTMAX 64
#define TPB 4                  // B-tiles per CTA; A tile stays resident
#define LDW 68                 // smem row stride in words: banks (4g+t)%32 distinct

__device__ float g_nsk[BMAX];
__device__ float g_nim[BMAX];
__device__ uint32_t g_skbf[BMAX * 64];                    // bf16x2-packed rows
__device__ uint32_t g_imbf[BMAX * 64];
__device__ float g_partial[(size_t)BMAX * NTMAX * 2];     // per (row, bn, wn-half)
__device__ float g_diag[BMAX];
__device__ float g_rowval[BMAX];

static __device__ __forceinline__ uint32_t s2u(const void* p) {
    uint32_t a;
    asm("{ .reg .u64 t; cvta.to.shared.u64 t, %1; cvt.u32.u64 %0, t; }" : "=r"(a) : "l"(p));
    return a;
}
static __device__ __forceinline__ void cpa16(uint32_t dst, const void* src) {
    asm volatile("cp.async.cg.shared.global [%0], [%1], 16;" :: "r"(dst), "l"(src) : "memory");
}
#define CP_COMMIT() asm volatile("cp.async.commit_group;" ::: "memory")
#define CP_WAIT0()  asm volatile("cp.async.wait_group 0;" ::: "memory")
#define CP_WAIT1()  asm volatile("cp.async.wait_group 1;" ::: "memory")

static __device__ __forceinline__ uint32_t packbf(float lo, float hi) {
    uint32_t r;
    asm("cvt.rn.bf16x2.f32 %0, %1, %2;" : "=r"(r) : "f"(hi), "f"(lo));
    return r;
}
static __device__ __forceinline__ void mma16(float* c, const uint32_t* a, const uint32_t* b) {
    asm("mma.sync.aligned.m16n8k16.row.col.f32.bf16.bf16.f32 "
        "{%0,%1,%2,%3}, {%4,%5,%6,%7}, {%8,%9}, {%0,%1,%2,%3};"
        : "+f"(c[0]), "+f"(c[1]), "+f"(c[2]), "+f"(c[3])
        : "r"(a[0]), "r"(a[1]), "r"(a[2]), "r"(a[3]), "r"(b[0]), "r"(b[1]));
}

// ---------------------------------------------------------------------------
// Fused: f32 row norms + bf16 conversion. One warp per row.
// ---------------------------------------------------------------------------
__global__ void convert_norms(const float* __restrict__ sk,
                              const float* __restrict__ im, int B) {
    int row = (blockIdx.x * blockDim.x + threadIdx.x) >> 5;
    int lane = threadIdx.x & 31;
    if (row >= B) return;
    const float* src = blockIdx.y ? im : sk;
    float* ndst = blockIdx.y ? g_nim : g_nsk;
    uint32_t* bdst = blockIdx.y ? g_imbf : g_skbf;
    float4 v = ((const float4*)(src + (size_t)row * DIM))[lane];
    bdst[row * 64 + lane * 2]     = packbf(v.x, v.y);
    bdst[row * 64 + lane * 2 + 1] = packbf(v.z, v.w);
    float s = v.x * v.x + v.y * v.y + v.z * v.z + v.w * v.w;
#pragma unroll
    for (int o = 16; o; o >>= 1) s += __shfl_xor_sync(0xffffffffu, s, o);
    if (lane == 0) ndst[row] = s;
}

// ---------------------------------------------------------------------------
// Software-pipelined bf16 MMA + fused distance/exp epilogue (occ 1).
// Epilogue of tile t-1 interleaved chunk-wise into mainloop of tile t,
// so MUFU and HMMA pipes run concurrently from each warp's stream.
// ---------------------------------------------------------------------------
__global__ void __launch_bounds__(256, 1)
dist_mma(int nt) {
    extern __shared__ uint32_t smw[];
    const uint32_t sbase = s2u(smw);
    uint32_t* As = smw;
    const uint32_t NORM_OFF = 3u * 128u * LDW;            // word offset of norm buffer
    float* nsm = (float*)(smw + NORM_OFF);                // 4*128 floats

    const int tid = threadIdx.x;
    const int wid = tid >> 5;
    const int lane = tid & 31;
    const int g = lane >> 2;
    const int t = lane & 3;
    const int wm = wid & 3;
    const int wn = wid >> 2;

    const int ntg = nt / TPB;
    const int bm = blockIdx.x / ntg;
    const int bn0 = (blockIdx.x % ntg) * TPB;

    // ---- prologue: A, B0, norms (group 0); B1 prefetch (group 1) ----
    {
        const uint32_t* Ag = g_skbf + (size_t)bm * TILE * 64;
        const uint32_t* Bg = g_imbf + (size_t)bn0 * TILE * 64;
#pragma unroll
        for (int it = 0; it < 8; it++) {
            int c = it * 256 + tid;
            int row = c >> 4, ch = c & 15;
            uint32_t doff = (uint32_t)row * 272 + (uint32_t)ch * 16;
            cpa16(sbase + doff, Ag + row * 64 + ch * 4);
            cpa16(sbase + 128 * LDW * 4 + doff, Bg + row * 64 + ch * 4);
        }
        if (tid < 128)
            cpa16(sbase + NORM_OFF * 4 + (uint32_t)tid * 16, g_nim + (size_t)bn0 * TILE + tid * 4);
        CP_COMMIT();
        const uint32_t* Bg1 = g_imbf + (size_t)(bn0 + 1) * TILE * 64;
#pragma unroll
        for (int it = 0; it < 8; it++) {
            int c = it * 256 + tid;
            int row = c >> 4, ch = c & 15;
            cpa16(sbase + 2 * 128 * LDW * 4 + (uint32_t)row * 272 + (uint32_t)ch * 16,
                  Bg1 + row * 64 + ch * 4);
        }
        CP_COMMIT();
        CP_WAIT1();
    }
    __syncthreads();

    float nr[2][2];
#pragma unroll
    for (int mt = 0; mt < 2; mt++)
#pragma unroll
        for (int h = 0; h < 2; h++)
            nr[mt][h] = g_nsk[bm * TILE + wm * 32 + mt * 16 + h * 8 + g];

    const int a_base = (wm * 32 + g) * LDW + t;
    const int b_base = (wn * 64 + g) * LDW + t;

    float acc[2][2][8][4];     // [buf][mt][nb][r]
    float rs[2][2];

#pragma unroll
    for (int tt = 0; tt <= TPB; tt++) {
        const bool do_main = (tt < TPB);
        const bool do_epi = (tt > 0);
        const int nbuf = tt & 1;
        const int bn_old = bn0 + tt - 1;

        // prefetch B[tt+1] into buffer (tt+1)&1
        if (tt + 1 < TPB) {
            const uint32_t* Bg = g_imbf + (size_t)(bn0 + tt + 1) * TILE * 64;
            uint32_t dbuf = sbase + (1 + ((tt + 1) & 1)) * 128 * LDW * 4;
#pragma unroll
            for (int it = 0; it < 8; it++) {
                int c = it * 256 + tid;
                int row = c >> 4, ch = c & 15;
                cpa16(dbuf + (uint32_t)row * 272 + (uint32_t)ch * 16, Bg + row * 64 + ch * 4);
            }
            CP_COMMIT();
        }

        float (*accN)[8][4] = acc[nbuf];
        float (*accO)[8][4] = acc[nbuf ^ 1];
        const uint32_t* Bs = smw + (1 + (tt & 1)) * 128 * LDW;

        if (do_main) {
#pragma unroll
            for (int mt = 0; mt < 2; mt++)
#pragma unroll
                for (int nb = 0; nb < 8; nb++)
#pragma unroll
                    for (int r = 0; r < 4; r++) accN[mt][nb][r] = 0.f;
        }
        if (do_epi) { rs[0][0] = rs[0][1] = rs[1][0] = rs[1][1] = 0.f; }

        const bool isdiag = do_epi && (bn_old == bm);

#pragma unroll
        for (int ks = 0; ks < 8; ks++) {
            if (do_main) {
                const int ko = ks * 8;
                uint32_t a[2][4], b[8][2];
#pragma unroll
                for (int mt = 0; mt < 2; mt++) {
                    int ba = a_base + mt * 16 * LDW + ko;
                    a[mt][0] = As[ba];
                    a[mt][1] = As[ba + 8 * LDW];
                    a[mt][2] = As[ba + 4];
                    a[mt][3] = As[ba + 8 * LDW + 4];
                }
#pragma unroll
                for (int nb = 0; nb < 8; nb++) {
                    int bb = b_base + nb * 8 * LDW + ko;
                    b[nb][0] = Bs[bb];
                    b[nb][1] = Bs[bb + 4];
                }
#pragma unroll
                for (int mt = 0; mt < 2; mt++)
#pragma unroll
                    for (int nb = 0; nb < 8; nb++) mma16(accN[mt][nb], a[mt], b[nb]);
            }
            if (do_epi) {
                // epilogue chunk nb=ks of the previous tile
                float2 nc = *(const float2*)&nsm[(tt - 1) * 128 + wn * 64 + ks * 8 + t * 2];
#pragma unroll
                for (int mt = 0; mt < 2; mt++) {
#pragma unroll
                    for (int h = 0; h < 2; h++) {
                        float base = nr[mt][h];
                        float sq0 = fmaxf(fmaf(-2.f, accO[mt][ks][h * 2 + 0], base + nc.x), 0.f);
                        float sq1 = fmaxf(fmaf(-2.f, accO[mt][ks][h * 2 + 1], base + nc.y), 0.f);
                        float d0, d1, e0, e1;
                        asm("sqrt.approx.f32 %0, %1;" : "=f"(d0) : "f"(sq0));
                        asm("sqrt.approx.f32 %0, %1;" : "=f"(d1) : "f"(sq1));
                        asm("ex2.approx.f32 %0, %1;" : "=f"(e0) : "f"(d0 * -1.4426950408889634f));
                        asm("ex2.approx.f32 %0, %1;" : "=f"(e1) : "f"(d1 * -1.4426950408889634f));
                        rs[mt][h] += e0 + e1;
                        if (isdiag) {
                            int r_local = wm * 32 + mt * 16 + h * 8 + g;
                            int jc = wn * 64 + ks * 8 + 2 * t;
                            if (jc == r_local) g_diag[bm * TILE + r_local] = d0;
                            if (jc + 1 == r_local) g_diag[bm * TILE + r_local] = d1;
                        }
                    }
                }
            }
        }

        if (do_epi) {
#pragma unroll
            for (int mt = 0; mt < 2; mt++) {
#pragma unroll
                for (int h = 0; h < 2; h++) {
                    float v = rs[mt][h];
                    v += __shfl_xor_sync(0xffffffffu, v, 1);
                    v += __shfl_xor_sync(0xffffffffu, v, 2);
                    if (t == 0) {
                        int r_local = wm * 32 + mt * 16 + h * 8 + g;
                        g_partial[((size_t)(bm * TILE + r_local) * nt + bn_old) * 2 + wn] = v;
                    }
                }
            }
        }

        if (do_main) {
            CP_WAIT0();
            __syncthreads();
        }
    }
}

// ---------------------------------------------------------------------------
// Per-row: log(sum of 2*nt partials) + diag (fixed order, deterministic)
// ---------------------------------------------------------------------------
__global__ void rows_kernel(int B, int nt) {
    int i = blockIdx.x * blockDim.x + threadIdx.x;
    if (i >= B) return;
    float s = 0.f;
    const float* p = g_partial + (size_t)i * nt * 2;
    for (int t = 0; t < 2 * nt; t++) s += p[t];
    g_rowval[i] = logf(s) + g_diag[i];
}

__global__ void final_kernel(float* __restrict__ out, int B, int out_size) {
    __shared__ float sm[1024];
    int tid = threadIdx.x;
    float s = 0.f;
    for (int i = tid; i < B; i += 1024) s += g_rowval[i];
    sm[tid] = s;
    __syncthreads();
    for (int o = 512; o; o >>= 1) {
        if (tid < o) sm[tid] += sm[tid + o];
        __syncthreads();
    }
    if (tid == 0) {
        float loss = sm[0] / (float)B;
        for (int i = 0; i < out_size; i++) out[i] = loss;
    }
}

extern "C" void kernel_launch(void* const* d_in, const int* in_sizes, int n_in,
                              void* d_out, int out_size) {
    const float* sk = (const float*)d_in[0];
    const float* im = (const float*)d_in[1];
    float* out = (float*)d_out;

    int B = in_sizes[0] / DIM;   // 8192
    int nt = B / TILE;           // 64

    convert_norms<<<dim3(B / 8, 2), 256>>>(sk, im, B);

    static const int SMEM_BYTES = (3 * 128 * LDW + 4 * 128) * 4;   // 106496
    cudaFuncSetAttribute(dist_mma, cudaFuncAttributeMaxDynamicSharedMemorySize, SMEM_BYTES);
    int ncta = nt * (nt / TPB);  // 1024
    dist_mma<<<ncta, 256, SMEM_BYTES>>>(nt);

    rows_kernel<<<(B + 255) / 256, 256>>>(B, nt);
    final_kernel<<<1, 1024>>>(out, B, out_size);
}